// round 10
// baseline (speedup 1.0000x reference)
#include <cuda_runtime.h>

#define T_STEPS 512
#define BATCH   4096
#define RING    128
#define RMASK   (RING - 1)
#define BLK     16
#define NBLK    (T_STEPS / BLK)   // 32
#define RBLK    (RING / BLK)      // 8

typedef unsigned long long ull;

__device__ __forceinline__ ull ffma2(ull a, ull b, ull c) {
    ull d; asm("fma.rn.f32x2 %0, %1, %2, %3;" : "=l"(d) : "l"(a), "l"(b), "l"(c)); return d;
}
__device__ __forceinline__ ull fadd2(ull a, ull b) {
    ull d; asm("add.rn.f32x2 %0, %1, %2;" : "=l"(d) : "l"(a), "l"(b)); return d;
}
__device__ __forceinline__ float hsum2(ull a) {
    float lo, hi; asm("mov.b64 {%0, %1}, %2;" : "=f"(lo), "=f"(hi) : "l"(a)); return lo + hi;
}
__device__ __forceinline__ ull pack2(float lo, float hi) {
    ull d; asm("mov.b64 %0, {%1, %2};" : "=l"(d) : "f"(lo), "f"(hi)); return d;
}
__device__ __forceinline__ float tanhapx(float x) {
    float y; asm("tanh.approx.f32 %0, %1;" : "=f"(y) : "f"(x)); return y;
}
__device__ __forceinline__ float sigapx(float x) {       // 0.5*tanh(x/2)+0.5
    return fmaf(0.5f, tanhapx(0.5f * x), 0.5f);
}
__device__ __forceinline__ unsigned ld_acq(const unsigned* p) {
    unsigned v;
    asm volatile("ld.acquire.cta.b32 %0, [%1];" : "=r"(v) : "l"(p) : "memory");
    return v;
}
__device__ __forceinline__ void st_rel(unsigned* p, unsigned v) {
    asm volatile("st.release.cta.b32 [%0], %1;" :: "l"(p), "r"(v) : "memory");
}
__device__ __forceinline__ void wait_ge(const unsigned* p, unsigned tgt) {
    if (ld_acq(p) >= tgt) return;
    while (ld_acq(p) < tgt) __nanosleep(64);
}

// 192 threads, 6 free-running warps, fully fused network:
//   w0: LSTM layer0 step j           (self-recurrent, publishes h0 ring)
//   w2: z[j] = Wih1*h0[j] + bias1    (h0 ring -> z ring, pure throughput)
//   w1: LSTM layer1 step j           (z ring + own h1 -> h2 ring)
//   w3,w4,w5: MLP 16->64->32->1 on h2[j], each takes part of a 16-step block,
//             writes out[j] directly.
// Sync: per-16-step-block release/acquire counters only; NO per-iteration
// barrier of any kind (warp-convergent bodies; per-warp LSU program order
// covers same-warp STS->LDS; shfl_syncs force reconvergence).
// LSTM lane scheme: lane = u + 16*hi; gate A = hi ({i,f}), gate B = hi+2
// ({g,o}); hi=0 lanes own (c,h).
__global__ void __launch_bounds__(192, 1) lstm_fused_kernel(
    const float* __restrict__ x,
    const float* __restrict__ Wih0, const float* __restrict__ Whh0,
    const float* __restrict__ bih0, const float* __restrict__ bhh0,
    const float* __restrict__ Wih1, const float* __restrict__ Whh1,
    const float* __restrict__ bih1, const float* __restrict__ bhh1,
    const float* __restrict__ W1,   const float* __restrict__ b1,
    const float* __restrict__ W2,   const float* __restrict__ b2,
    const float* __restrict__ W3,   const float* __restrict__ b3,
    float* __restrict__ out)
{
    __shared__ float x_sh[T_STEPS];
    __shared__ __align__(16) float h0ring[RING][16];
    __shared__ __align__(16) float zring[RING][64];
    __shared__ __align__(16) float h2ring[RING][16];
    __shared__ __align__(16) float h1buf[2][16];
    __shared__ __align__(16) float z1sh[3][64];
    __shared__ unsigned cnt[6];  // [0]=w0 [1]=w2 [2]=w1 [3..5]=mlp warps

    const int tid  = threadIdx.x;
    const int w    = tid >> 5;
    const int lane = tid & 31;
    const int u    = lane & 15;
    const int hi   = lane >> 4;

    // ---- init ----
#pragma unroll
    for (int r = 0; r < 3; r++) {
        const int idx = tid + 192 * r;
        if (idx < T_STEPS) x_sh[idx] = x[idx * BATCH + (BATCH - 1)];
    }
    if (tid < 16) h0ring[RING - 1][tid] = 0.0f;
    if (tid < 32) ((float*)h1buf)[tid] = 0.0f;
    if (tid < 6)  cnt[tid] = 0;

    if (w < 3) {
        // =========================== LSTM warps ===========================
        const int giA = hi * 16 + u;
        const int giB = (hi + 2) * 16 + u;
        ull WA[8], WB[8];
        float biasA = 0.f, biasB = 0.f, wxA = 0.f, wxB = 0.f;
        if (w == 0) {
            const ull* Wp = (const ull*)Whh0;
#pragma unroll
            for (int k = 0; k < 8; k++) { WA[k] = Wp[giA * 8 + k]; WB[k] = Wp[giB * 8 + k]; }
            biasA = bih0[giA] + bhh0[giA];  biasB = bih0[giB] + bhh0[giB];
            wxA   = Wih0[giA];              wxB   = Wih0[giB];
        } else if (w == 2) {
            const ull* Wp = (const ull*)Wih1;
#pragma unroll
            for (int k = 0; k < 8; k++) { WA[k] = Wp[giA * 8 + k]; WB[k] = Wp[giB * 8 + k]; }
            biasA = bih1[giA] + bhh1[giA];  biasB = bih1[giB] + bhh1[giB];
        } else {
            const ull* Wp = (const ull*)Whh1;
#pragma unroll
            for (int k = 0; k < 8; k++) { WA[k] = Wp[giA * 8 + k]; WB[k] = Wp[giB * 8 + k]; }
        }
        const float sB  = (hi == 0) ? 1.0f : 0.5f;
        const float pmB = (hi == 0) ? 1.0f : 0.5f;
        const float paB = (hi == 0) ? 0.0f : 0.5f;

        __syncthreads();

        if (w == 0) {
            // ---- layer0 ----
            float h = 0.f, c = 0.f;
            for (int b = 0; b < NBLK; b++) {
                if (b >= RBLK) wait_ge(&cnt[1], b - RBLK + 1);
#pragma unroll 2
                for (int jj = 0; jj < BLK; jj++) {
                    const int j = b * BLK + jj;
                    const ulonglong2* hp = (const ulonglong2*)h0ring[(j + RING - 1) & RMASK];
                    const ulonglong2 t0 = hp[0], t1 = hp[1], t2 = hp[2], t3 = hp[3];
                    const ull op[8] = { t0.x, t0.y, t1.x, t1.y, t2.x, t2.y, t3.x, t3.y };
                    const float xv = x_sh[j];

                    ull a0 = ffma2(WA[0], op[0], pack2(fmaf(wxA, xv, biasA), 0.f));
                    ull a1 = ffma2(WA[1], op[1], 0ull);
                    ull b0 = ffma2(WB[0], op[0], pack2(fmaf(wxB, xv, biasB), 0.f));
                    ull b1 = ffma2(WB[1], op[1], 0ull);
#pragma unroll
                    for (int k = 2; k < 8; k += 2) {
                        a0 = ffma2(WA[k], op[k], a0);  a1 = ffma2(WA[k + 1], op[k + 1], a1);
                        b0 = ffma2(WB[k], op[k], b0);  b1 = ffma2(WB[k + 1], op[k + 1], b1);
                    }
                    const float aA = hsum2(fadd2(a0, a1));
                    const float aB = hsum2(fadd2(b0, b1));
                    const float vA = sigapx(aA);
                    const float vB = fmaf(pmB, tanhapx(sB * aB), paB);
                    const float fv = __shfl_sync(0xffffffffu, vA, lane | 16);
                    const float ov = __shfl_sync(0xffffffffu, vB, lane | 16);
                    c = fmaf(fv, c, vA * vB);
                    h = ov * tanhapx(c);
                    if (hi == 0) h0ring[j & RMASK][u] = h;
                }
                __syncwarp();
                if (lane == 0) st_rel(&cnt[0], b + 1);
            }
        } else if (w == 2) {
            // ---- z producer ----
            for (int b = 0; b < NBLK; b++) {
                wait_ge(&cnt[0], b + 1);
                if (b >= RBLK) wait_ge(&cnt[2], b - RBLK + 1);
#pragma unroll 4
                for (int jj = 0; jj < BLK; jj++) {
                    const int j = b * BLK + jj;
                    const ulonglong2* hp = (const ulonglong2*)h0ring[j & RMASK];
                    const ulonglong2 t0 = hp[0], t1 = hp[1], t2 = hp[2], t3 = hp[3];
                    const ull op[8] = { t0.x, t0.y, t1.x, t1.y, t2.x, t2.y, t3.x, t3.y };

                    ull a0 = ffma2(WA[0], op[0], pack2(biasA, 0.f));
                    ull a1 = ffma2(WA[1], op[1], 0ull);
                    ull b0 = ffma2(WB[0], op[0], pack2(biasB, 0.f));
                    ull b1 = ffma2(WB[1], op[1], 0ull);
#pragma unroll
                    for (int k = 2; k < 8; k += 2) {
                        a0 = ffma2(WA[k], op[k], a0);  a1 = ffma2(WA[k + 1], op[k + 1], a1);
                        b0 = ffma2(WB[k], op[k], b0);  b1 = ffma2(WB[k + 1], op[k + 1], b1);
                    }
                    zring[j & RMASK][giA] = hsum2(fadd2(a0, a1));
                    zring[j & RMASK][giB] = hsum2(fadd2(b0, b1));
                }
                __syncwarp();
                if (lane == 0) st_rel(&cnt[1], b + 1);
            }
        } else {
            // ---- layer1 ----
            float h = 0.f, c = 0.f;
            for (int b = 0; b < NBLK; b++) {
                wait_ge(&cnt[1], b + 1);
                if (b >= RBLK) {
                    wait_ge(&cnt[3], b - RBLK + 1);
                    wait_ge(&cnt[4], b - RBLK + 1);
                    wait_ge(&cnt[5], b - RBLK + 1);
                }
#pragma unroll 2
                for (int jj = 0; jj < BLK; jj++) {
                    const int j = b * BLK + jj;
                    const ulonglong2* hp = (const ulonglong2*)h1buf[j & 1];
                    const ulonglong2 t0 = hp[0], t1 = hp[1], t2 = hp[2], t3 = hp[3];
                    const ull op[8] = { t0.x, t0.y, t1.x, t1.y, t2.x, t2.y, t3.x, t3.y };
                    const float zA = zring[j & RMASK][giA];
                    const float zB = zring[j & RMASK][giB];

                    ull a0 = ffma2(WA[0], op[0], pack2(zA, 0.f));
                    ull a1 = ffma2(WA[1], op[1], 0ull);
                    ull b0 = ffma2(WB[0], op[0], pack2(zB, 0.f));
                    ull b1 = ffma2(WB[1], op[1], 0ull);
#pragma unroll
                    for (int k = 2; k < 8; k += 2) {
                        a0 = ffma2(WA[k], op[k], a0);  a1 = ffma2(WA[k + 1], op[k + 1], a1);
                        b0 = ffma2(WB[k], op[k], b0);  b1 = ffma2(WB[k + 1], op[k + 1], b1);
                    }
                    const float aA = hsum2(fadd2(a0, a1));
                    const float aB = hsum2(fadd2(b0, b1));
                    const float vA = sigapx(aA);
                    const float vB = fmaf(pmB, tanhapx(sB * aB), paB);
                    const float fv = __shfl_sync(0xffffffffu, vA, lane | 16);
                    const float ov = __shfl_sync(0xffffffffu, vB, lane | 16);
                    c = fmaf(fv, c, vA * vB);
                    h = ov * tanhapx(c);
                    if (hi == 0) {
                        h1buf[(j + 1) & 1][u] = h;
                        h2ring[j & RMASK][u] = h;
                    }
                }
                __syncwarp();
                if (lane == 0) st_rel(&cnt[2], b + 1);
            }
        }
    } else {
        // =========================== MLP warps ===========================
        const int mw = w - 3;                 // 0,1,2
        const int jlo = mw * 6;               // 0..5 / 6..11 / 12..15
        const int jhi = (mw == 2) ? BLK : jlo + 6;

        ull W1a[8], W1b[8], W2r[32];
        {
            const ull* Wp = (const ull*)W1;
#pragma unroll
            for (int k = 0; k < 8; k++) {
                W1a[k] = Wp[lane * 8 + k];
                W1b[k] = Wp[(lane + 32) * 8 + k];
            }
            const ull* W2p = (const ull*)W2;
#pragma unroll
            for (int k = 0; k < 32; k++) W2r[k] = W2p[lane * 32 + k];
        }
        const float b1a = b1[lane], b1b = b1[lane + 32];
        const float b2r = b2[lane];
        const float w3r = W3[lane];
        const float b3r = b3[0];
        float* z1w = z1sh[mw];

        __syncthreads();

        for (int b = 0; b < NBLK; b++) {
            wait_ge(&cnt[2], b + 1);
            for (int jj = jlo; jj < jhi; jj++) {
                const int j = b * BLK + jj;
                const ulonglong2* hp = (const ulonglong2*)h2ring[j & RMASK];
                const ulonglong2 t0 = hp[0], t1 = hp[1], t2 = hp[2], t3 = hp[3];
                const ull op[8] = { t0.x, t0.y, t1.x, t1.y, t2.x, t2.y, t3.x, t3.y };

                // layer1: two outputs per lane
                ull a0 = ffma2(W1a[0], op[0], 0ull);
                ull a1 = ffma2(W1a[1], op[1], 0ull);
                ull b0 = ffma2(W1b[0], op[0], 0ull);
                ull b1v = ffma2(W1b[1], op[1], 0ull);
#pragma unroll
                for (int k = 2; k < 8; k += 2) {
                    a0 = ffma2(W1a[k], op[k], a0);  a1 = ffma2(W1a[k + 1], op[k + 1], a1);
                    b0 = ffma2(W1b[k], op[k], b0);  b1v = ffma2(W1b[k + 1], op[k + 1], b1v);
                }
                z1w[lane]      = fmaxf(hsum2(fadd2(a0, a1)) + b1a, 0.0f);
                z1w[lane + 32] = fmaxf(hsum2(fadd2(b0, b1v)) + b1b, 0.0f);
                __syncwarp();

                // layer2 (64-dot per lane) + folded layer3
                const ulonglong2* zp = (const ulonglong2*)z1w;
                ull c0 = 0ull, c1 = 0ull, c2 = 0ull, c3 = 0ull;
#pragma unroll
                for (int q = 0; q < 4; q++) {
                    const ulonglong2 v0 = zp[4 * q], v1 = zp[4 * q + 1],
                                     v2 = zp[4 * q + 2], v3 = zp[4 * q + 3];
                    c0 = ffma2(W2r[8 * q    ], v0.x, c0);
                    c0 = ffma2(W2r[8 * q + 1], v0.y, c0);
                    c1 = ffma2(W2r[8 * q + 2], v1.x, c1);
                    c1 = ffma2(W2r[8 * q + 3], v1.y, c1);
                    c2 = ffma2(W2r[8 * q + 4], v2.x, c2);
                    c2 = ffma2(W2r[8 * q + 5], v2.y, c2);
                    c3 = ffma2(W2r[8 * q + 6], v3.x, c3);
                    c3 = ffma2(W2r[8 * q + 7], v3.y, c3);
                }
                const float a2 = hsum2(fadd2(fadd2(c0, c1), fadd2(c2, c3))) + b2r;
                float v = fmaxf(a2, 0.0f) * w3r;
#pragma unroll
                for (int off = 16; off; off >>= 1)
                    v += __shfl_xor_sync(0xffffffffu, v, off);
                if (lane == 0) out[j] = v + b3r;
                __syncwarp();
            }
            __syncwarp();
            if (lane == 0) st_rel(&cnt[3 + mw], b + 1);
        }
    }
}

extern "C" void kernel_launch(void* const* d_in, const int* in_sizes, int n_in,
                              void* d_out, int out_size)
{
    const float* x    = (const float*)d_in[0];
    const float* Wih0 = (const float*)d_in[1];
    const float* Whh0 = (const float*)d_in[2];
    const float* bih0 = (const float*)d_in[3];
    const float* bhh0 = (const float*)d_in[4];
    const float* Wih1 = (const float*)d_in[5];
    const float* Whh1 = (const float*)d_in[6];
    const float* bih1 = (const float*)d_in[7];
    const float* bhh1 = (const float*)d_in[8];
    const float* W1   = (const float*)d_in[9];
    const float* b1   = (const float*)d_in[10];
    const float* W2   = (const float*)d_in[11];
    const float* b2   = (const float*)d_in[12];
    const float* W3   = (const float*)d_in[13];
    const float* b3   = (const float*)d_in[14];
    float* out = (float*)d_out;

    lstm_fused_kernel<<<1, 192>>>(x, Wih0, Whh0, bih0, bhh0,
                                  Wih1, Whh1, bih1, bhh1,
                                  W1, b1, W2, b2, W3, b3, out);
}